// round 2
// baseline (speedup 1.0000x reference)
#include <cuda_runtime.h>
#include <math.h>

#define NN 100000
#define EE 1000000
#define FIN 500
#define HH 64
#define HB 128   /* 2H */
#define CC 3
#define EPS_MSG 1e-7f
#define LN_EPS  1e-5f

// ---------------- device scratch (no allocations allowed) ----------------
static __device__ float g_h  [(size_t)NN*HH];   // current node features
static __device__ float g_tmp[(size_t)NN*HH];   // agg + x (MLP input)
static __device__ float g_h1 [(size_t)NN*HB];   // MLP hidden (128 wide)
static __device__ int   g_rowptr[NN+1];
static __device__ int   g_fill[NN];
static __device__ int   g_scan[NN];
static __device__ int   g_esrc[EE];
static __device__ int   g_bsums[128];
static __device__ int   g_is64;

// ---------------- edge dtype detection ----------------
__global__ void k_detect(const void* ei){
  if(blockIdx.x==0 && threadIdx.x==0){
    const long long* p=(const long long*)ei;
    int ok=1;
    #pragma unroll
    for(int i=0;i<8;i++){ long long v=p[i]; if(v<0||v>=NN) ok=0; }
    g_is64=ok;
  }
}

__device__ __forceinline__ int edge_src(const void* ei,int e){
  return g_is64 ? (int)((const long long*)ei)[e] : ((const int*)ei)[e];
}
__device__ __forceinline__ int edge_dst(const void* ei,int e){
  return g_is64 ? (int)((const long long*)ei)[EE+e] : ((const int*)ei)[EE+e];
}

// ---------------- CSR build ----------------
__global__ void k_zero(){
  int i=blockIdx.x*blockDim.x+threadIdx.x;
  if(i<NN) g_fill[i]=0;
}
__global__ void k_hist(const void* ei){
  int e=blockIdx.x*blockDim.x+threadIdx.x;
  if(e>=EE) return;
  atomicAdd(&g_fill[edge_dst(ei,e)],1);
}

__device__ __forceinline__ int block_incl_scan(int v){
  int lane=threadIdx.x&31, wid=threadIdx.x>>5;
  int x=v;
  #pragma unroll
  for(int o=1;o<32;o<<=1){ int y=__shfl_up_sync(0xffffffffu,x,o); if(lane>=o) x+=y; }
  __shared__ int ws[32];
  if(lane==31) ws[wid]=x;
  __syncthreads();
  int nw=(blockDim.x+31)>>5;
  if(wid==0){
    int y=(lane<nw)? ws[lane]:0;
    #pragma unroll
    for(int o=1;o<32;o<<=1){ int z=__shfl_up_sync(0xffffffffu,y,o); if(lane>=o) y+=z; }
    ws[lane]=y;
  }
  __syncthreads();
  return x + (wid>0? ws[wid-1]:0);
}

__global__ void k_scan1(){   // 98 blocks x 1024
  int i=blockIdx.x*1024+threadIdx.x;
  int v=(i<NN)? g_fill[i]:0;
  int incl=block_incl_scan(v);
  if(i<NN) g_scan[i]=incl;
  if(threadIdx.x==1023) g_bsums[blockIdx.x]=incl;
}
__global__ void k_scan2(){   // 1 block x 128, NB=98
  int t=threadIdx.x;
  int v=(t<98)? g_bsums[t]:0;
  int incl=block_incl_scan(v);
  if(t<98) g_bsums[t]=incl-v;   // exclusive
}
__global__ void k_scan3(){
  int i=blockIdx.x*blockDim.x+threadIdx.x;
  if(i>=NN) return;
  int c=g_fill[i];
  int incl=g_scan[i]+g_bsums[i>>10];
  g_rowptr[i+1]=incl;
  g_fill[i]=incl-c;             // start offset for scatter
  if(i==0) g_rowptr[0]=0;
}
__global__ void k_scatter(const void* ei){
  int e=blockIdx.x*blockDim.x+threadIdx.x;
  if(e>=EE) return;
  int s=edge_src(ei,e);
  int d=edge_dst(ei,e);
  int pos=atomicAdd(&g_fill[d],1);
  g_esrc[pos]=s;
}

// ---------------- encoder GEMM: g_h = x @ enc_W + enc_b ----------------
__global__ void __launch_bounds__(256) k_enc(const float* __restrict__ x,
                                             const float* __restrict__ W,
                                             const float* __restrict__ bias){
  __shared__ float As[16][132];
  __shared__ float Bs[16][64];
  const int tid=threadIdx.x;
  const int tx=tid&15, ty=tid>>4;
  const int rowBase=blockIdx.x*128;
  float acc[8][4];
  #pragma unroll
  for(int i=0;i<8;i++)
    #pragma unroll
    for(int j=0;j<4;j++) acc[i][j]=0.f;

  for(int kb=0;kb<512;kb+=16){
    #pragma unroll
    for(int q0=0;q0<2;q0++){
      int q=tid+q0*256;
      int r=q>>2, kq=(q&3)<<2;
      int gr=rowBase+r;
      float4 v=make_float4(0.f,0.f,0.f,0.f);
      if(gr<NN && kb+kq<FIN)
        v=*(const float4*)(x+(size_t)gr*FIN+kb+kq);
      As[kq+0][r]=v.x; As[kq+1][r]=v.y; As[kq+2][r]=v.z; As[kq+3][r]=v.w;
    }
    {
      int kr=tid>>4, c4=(tid&15)<<2;
      float4 v=make_float4(0.f,0.f,0.f,0.f);
      if(kb+kr<FIN) v=*(const float4*)(W+(size_t)(kb+kr)*HH+c4);
      *(float4*)&Bs[kr][c4]=v;
    }
    __syncthreads();
    #pragma unroll
    for(int kk=0;kk<16;kk++){
      float4 a0=*(const float4*)&As[kk][ty*8];
      float4 a1=*(const float4*)&As[kk][ty*8+4];
      float4 b =*(const float4*)&Bs[kk][tx*4];
      float ar[8]={a0.x,a0.y,a0.z,a0.w,a1.x,a1.y,a1.z,a1.w};
      float br[4]={b.x,b.y,b.z,b.w};
      #pragma unroll
      for(int i=0;i<8;i++)
        #pragma unroll
        for(int j=0;j<4;j++) acc[i][j]=fmaf(ar[i],br[j],acc[i][j]);
    }
    __syncthreads();
  }
  float4 bv=*(const float4*)(bias+tx*4);
  float bb[4]={bv.x,bv.y,bv.z,bv.w};
  #pragma unroll
  for(int i=0;i<8;i++){
    int gr=rowBase+ty*8+i;
    if(gr<NN){
      float4 o;
      o.x=acc[i][0]+bb[0]; o.y=acc[i][1]+bb[1];
      o.z=acc[i][2]+bb[2]; o.w=acc[i][3]+bb[3];
      *(float4*)(g_h+(size_t)gr*HH+tx*4)=o;
    }
  }
}

// ---------------- softmax aggregation (warp per node) ----------------
// g_tmp[n] = (sum_e m*softmax) + g_h[n],  m = relu(g_h[src])+eps, z = m*t
__global__ void k_agg(const float* __restrict__ tptr){
  int gw=(blockIdx.x*blockDim.x+threadIdx.x)>>5;
  if(gw>=NN) return;
  int lane=threadIdx.x&31;
  float tv=*tptr;
  int s0=g_rowptr[gw], s1=g_rowptr[gw+1];
  float zm0=-3.0e38f, zm1=-3.0e38f;
  for(int base=s0;base<s1;base+=32){
    int cnt=min(32,s1-base);
    int idx=(base+lane<s1)? g_esrc[base+lane]:0;
    for(int j=0;j<cnt;j++){
      int s=__shfl_sync(0xffffffffu,idx,j);
      float2 v=*(const float2*)(g_h+(size_t)s*HH+2*lane);
      float m0=fmaxf(v.x,0.f)+EPS_MSG;
      float m1=fmaxf(v.y,0.f)+EPS_MSG;
      zm0=fmaxf(zm0,m0*tv);
      zm1=fmaxf(zm1,m1*tv);
    }
  }
  float den0=0.f,den1=0.f,num0=0.f,num1=0.f;
  for(int base=s0;base<s1;base+=32){
    int cnt=min(32,s1-base);
    int idx=(base+lane<s1)? g_esrc[base+lane]:0;
    for(int j=0;j<cnt;j++){
      int s=__shfl_sync(0xffffffffu,idx,j);
      float2 v=*(const float2*)(g_h+(size_t)s*HH+2*lane);
      float m0=fmaxf(v.x,0.f)+EPS_MSG;
      float m1=fmaxf(v.y,0.f)+EPS_MSG;
      float a0=__expf(m0*tv-zm0);
      float a1=__expf(m1*tv-zm1);
      den0+=a0; den1+=a1;
      num0=fmaf(m0,a0,num0);
      num1=fmaf(m1,a1,num1);
    }
  }
  float2 hv=*(const float2*)(g_h+(size_t)gw*HH+2*lane);
  float o0=(s1>s0)? num0/den0:0.f;
  float o1=(s1>s0)? num1/den1:0.f;
  float2 o; o.x=o0+hv.x; o.y=o1+hv.y;
  *(float2*)(g_tmp+(size_t)gw*HH+2*lane)=o;
}

// ---------------- MLP GEMM1 fused: g_h1 = relu(LN(g_tmp@W1+b1,g,be)) ----------------
__global__ void __launch_bounds__(256) k_mlp1(const float* __restrict__ W,
                                              const float* __restrict__ b,
                                              const float* __restrict__ gma,
                                              const float* __restrict__ bet){
  __shared__ float As[32][68];
  __shared__ float Bs[32][128];
  const int tid=threadIdx.x;
  const int tx=tid&31, ty=tid>>5;
  const int rowBase=blockIdx.x*64;
  float acc[8][4];
  #pragma unroll
  for(int i=0;i<8;i++)
    #pragma unroll
    for(int j=0;j<4;j++) acc[i][j]=0.f;

  #pragma unroll
  for(int kb=0;kb<64;kb+=32){
    #pragma unroll
    for(int q0=0;q0<2;q0++){
      int q=tid+q0*256;
      int r=q>>3, kq=(q&7)<<2;
      int gr=rowBase+r;
      float4 v=(gr<NN)? *(const float4*)(g_tmp+(size_t)gr*HH+kb+kq)
                      : make_float4(0.f,0.f,0.f,0.f);
      As[kq+0][r]=v.x; As[kq+1][r]=v.y; As[kq+2][r]=v.z; As[kq+3][r]=v.w;
    }
    #pragma unroll
    for(int q0=0;q0<4;q0++){
      int q=tid+q0*256;
      int kr=q>>5, c4=(q&31)<<2;
      *(float4*)&Bs[kr][c4]=*(const float4*)(W+(size_t)(kb+kr)*HB+c4);
    }
    __syncthreads();
    #pragma unroll
    for(int kk=0;kk<32;kk++){
      float4 a0=*(const float4*)&As[kk][ty*8];
      float4 a1=*(const float4*)&As[kk][ty*8+4];
      float4 bv=*(const float4*)&Bs[kk][tx*4];
      float ar[8]={a0.x,a0.y,a0.z,a0.w,a1.x,a1.y,a1.z,a1.w};
      float br[4]={bv.x,bv.y,bv.z,bv.w};
      #pragma unroll
      for(int i=0;i<8;i++)
        #pragma unroll
        for(int j=0;j<4;j++) acc[i][j]=fmaf(ar[i],br[j],acc[i][j]);
    }
    __syncthreads();
  }
  float4 bv=*(const float4*)(b+tx*4);
  float4 gv=*(const float4*)(gma+tx*4);
  float4 ev=*(const float4*)(bet+tx*4);
  float bb[4]={bv.x,bv.y,bv.z,bv.w};
  float gg[4]={gv.x,gv.y,gv.z,gv.w};
  float ee[4]={ev.x,ev.y,ev.z,ev.w};
  #pragma unroll
  for(int i=0;i<8;i++){
    float c0=acc[i][0]+bb[0], c1=acc[i][1]+bb[1];
    float c2=acc[i][2]+bb[2], c3=acc[i][3]+bb[3];
    float s=c0+c1+c2+c3;
    float ss=c0*c0+c1*c1+c2*c2+c3*c3;
    #pragma unroll
    for(int o=16;o>0;o>>=1){
      s +=__shfl_xor_sync(0xffffffffu,s ,o);
      ss+=__shfl_xor_sync(0xffffffffu,ss,o);
    }
    float mu=s*(1.f/128.f);
    float var=ss*(1.f/128.f)-mu*mu;
    float rstd=rsqrtf(var+LN_EPS);
    float o0=fmaxf((c0-mu)*rstd*gg[0]+ee[0],0.f);
    float o1=fmaxf((c1-mu)*rstd*gg[1]+ee[1],0.f);
    float o2=fmaxf((c2-mu)*rstd*gg[2]+ee[2],0.f);
    float o3=fmaxf((c3-mu)*rstd*gg[3]+ee[3],0.f);
    int gr=rowBase+ty*8+i;
    if(gr<NN){
      float4 o; o.x=o0; o.y=o1; o.z=o2; o.w=o3;
      *(float4*)(g_h1+(size_t)gr*HB+tx*4)=o;
    }
  }
}

// ---------------- MLP GEMM2 fused ----------------
// mode 0: g_h = g_h1@W2 + b2
// mode 1: g_h += relu(LN(g_h1@W2 + b2, ng, nb))
__global__ void __launch_bounds__(256) k_mlp2(const float* __restrict__ W,
                                              const float* __restrict__ b,
                                              const float* __restrict__ gma,
                                              const float* __restrict__ bet,
                                              int mode){
  __shared__ float As[32][68];
  __shared__ float Bs[32][64];
  const int tid=threadIdx.x;
  const int tx=tid&31, ty=tid>>5;
  const int rowBase=blockIdx.x*64;
  float acc[8][2];
  #pragma unroll
  for(int i=0;i<8;i++){ acc[i][0]=0.f; acc[i][1]=0.f; }

  #pragma unroll
  for(int kb=0;kb<128;kb+=32){
    #pragma unroll
    for(int q0=0;q0<2;q0++){
      int q=tid+q0*256;
      int r=q>>3, kq=(q&7)<<2;
      int gr=rowBase+r;
      float4 v=(gr<NN)? *(const float4*)(g_h1+(size_t)gr*HB+kb+kq)
                      : make_float4(0.f,0.f,0.f,0.f);
      As[kq+0][r]=v.x; As[kq+1][r]=v.y; As[kq+2][r]=v.z; As[kq+3][r]=v.w;
    }
    #pragma unroll
    for(int q0=0;q0<2;q0++){
      int q=tid+q0*256;
      int kr=q>>4, c4=(q&15)<<2;
      *(float4*)&Bs[kr][c4]=*(const float4*)(W+(size_t)(kb+kr)*HH+c4);
    }
    __syncthreads();
    #pragma unroll
    for(int kk=0;kk<32;kk++){
      float4 a0=*(const float4*)&As[kk][ty*8];
      float4 a1=*(const float4*)&As[kk][ty*8+4];
      float2 bv=*(const float2*)&Bs[kk][tx*2];
      float ar[8]={a0.x,a0.y,a0.z,a0.w,a1.x,a1.y,a1.z,a1.w};
      #pragma unroll
      for(int i=0;i<8;i++){
        acc[i][0]=fmaf(ar[i],bv.x,acc[i][0]);
        acc[i][1]=fmaf(ar[i],bv.y,acc[i][1]);
      }
    }
    __syncthreads();
  }
  float2 b2v=*(const float2*)(b+tx*2);
  #pragma unroll
  for(int i=0;i<8;i++){
    float c0=acc[i][0]+b2v.x, c1=acc[i][1]+b2v.y;
    int gr=rowBase+ty*8+i;
    if(mode==0){
      if(gr<NN){
        float2 o; o.x=c0; o.y=c1;
        *(float2*)(g_h+(size_t)gr*HH+tx*2)=o;
      }
    }else{
      float s=c0+c1, ss=c0*c0+c1*c1;
      #pragma unroll
      for(int o=16;o>0;o>>=1){
        s +=__shfl_xor_sync(0xffffffffu,s ,o);
        ss+=__shfl_xor_sync(0xffffffffu,ss,o);
      }
      float mu=s*(1.f/64.f);
      float var=ss*(1.f/64.f)-mu*mu;
      float rstd=rsqrtf(var+LN_EPS);
      float2 gv=*(const float2*)(gma+tx*2);
      float2 ev=*(const float2*)(bet+tx*2);
      float v0=fmaxf((c0-mu)*rstd*gv.x+ev.x,0.f);
      float v1=fmaxf((c1-mu)*rstd*gv.y+ev.y,0.f);
      if(gr<NN){
        float2 old=*(const float2*)(g_h+(size_t)gr*HH+tx*2);
        float2 o; o.x=old.x+v0; o.y=old.y+v1;
        *(float2*)(g_h+(size_t)gr*HH+tx*2)=o;
      }
    }
  }
}

// ---------------- final: out = relu(LN(g_h, ng0, nb0)) @ lin_W + lin_b ----------------
__global__ void k_final(const float* __restrict__ ng0,
                        const float* __restrict__ nb0,
                        const float* __restrict__ lw,
                        const float* __restrict__ lb,
                        float* __restrict__ out){
  int gw=(blockIdx.x*blockDim.x+threadIdx.x)>>5;
  if(gw>=NN) return;
  int lane=threadIdx.x&31;
  float2 hv=*(const float2*)(g_h+(size_t)gw*HH+2*lane);
  float s=hv.x+hv.y, ss=hv.x*hv.x+hv.y*hv.y;
  #pragma unroll
  for(int o=16;o>0;o>>=1){
    s +=__shfl_xor_sync(0xffffffffu,s ,o);
    ss+=__shfl_xor_sync(0xffffffffu,ss,o);
  }
  float mu=s*(1.f/64.f);
  float var=ss*(1.f/64.f)-mu*mu;
  float rstd=rsqrtf(var+LN_EPS);
  float r0=fmaxf((hv.x-mu)*rstd*ng0[2*lane  ]+nb0[2*lane  ],0.f);
  float r1=fmaxf((hv.y-mu)*rstd*ng0[2*lane+1]+nb0[2*lane+1],0.f);
  float p0=r0*lw[(2*lane)*CC+0]+r1*lw[(2*lane+1)*CC+0];
  float p1=r0*lw[(2*lane)*CC+1]+r1*lw[(2*lane+1)*CC+1];
  float p2=r0*lw[(2*lane)*CC+2]+r1*lw[(2*lane+1)*CC+2];
  #pragma unroll
  for(int o=16;o>0;o>>=1){
    p0+=__shfl_xor_sync(0xffffffffu,p0,o);
    p1+=__shfl_xor_sync(0xffffffffu,p1,o);
    p2+=__shfl_xor_sync(0xffffffffu,p2,o);
  }
  if(lane==0){
    out[(size_t)gw*CC+0]=p0+lb[0];
    out[(size_t)gw*CC+1]=p1+lb[1];
    out[(size_t)gw*CC+2]=p2+lb[2];
  }
}

// ---------------- launch ----------------
extern "C" void kernel_launch(void* const* d_in, const int* in_sizes, int n_in,
                              void* d_out, int out_size){
  const float* x    =(const float*)d_in[0];
  const void * ei   =              d_in[1];
  const float* encW =(const float*)d_in[2];
  const float* encB =(const float*)d_in[3];
  const float* W1   =(const float*)d_in[4];
  const float* b1   =(const float*)d_in[5];
  const float* g1   =(const float*)d_in[6];
  const float* be1  =(const float*)d_in[7];
  const float* W2   =(const float*)d_in[8];
  const float* b2   =(const float*)d_in[9];
  const float* t    =(const float*)d_in[10];
  const float* ng   =(const float*)d_in[11];
  const float* nb   =(const float*)d_in[12];
  const float* linW =(const float*)d_in[13];
  const float* linB =(const float*)d_in[14];
  float* out=(float*)d_out;

  // CSR build
  k_detect<<<1,32>>>(ei);
  k_zero  <<<(NN+255)/256,256>>>();
  k_hist  <<<(EE+511)/512,512>>>(ei);
  k_scan1 <<<98,1024>>>();
  k_scan2 <<<1,128>>>();
  k_scan3 <<<(NN+255)/256,256>>>();
  k_scatter<<<(EE+511)/512,512>>>(ei);

  // encoder
  k_enc<<<(NN+127)/128,256>>>(x,encW,encB);

  const int gemmBlocks=(NN+63)/64;
  const int warpBlocks=(NN*32+255)/256;

  // pre-loop conv with layer-0 params: h = conv(h)
  k_agg <<<warpBlocks,256>>>(t+0);
  k_mlp1<<<gemmBlocks,256>>>(W1, b1, g1, be1);
  k_mlp2<<<gemmBlocks,256>>>(W2, b2, ng, nb, 0);

  // residual layers: h = h + relu(LN_l(conv_l(h)))
  for(int l=0;l<3;l++){
    k_agg <<<warpBlocks,256>>>(t+l);
    k_mlp1<<<gemmBlocks,256>>>(W1+(size_t)l*HH*HB, b1+(size_t)l*HB,
                               g1+(size_t)l*HB,   be1+(size_t)l*HB);
    k_mlp2<<<gemmBlocks,256>>>(W2+(size_t)l*HB*HH, b2+(size_t)l*HH,
                               ng+(size_t)l*HH,    nb+(size_t)l*HH, 1);
  }

  // head uses ng[0], nb[0]
  k_final<<<warpBlocks,256>>>(ng, nb, linW, linB, out);
}